// round 7
// baseline (speedup 1.0000x reference)
#include <cuda_runtime.h>

#define N_CLASS  100
#define N_CENTER 4
#define HIDDEN   128
#define BATCH    2048
#define CHUNK    8

// Scratch (device globals; no runtime allocation allowed).
__device__ float g_S[N_CLASS * HIDDEN * HIDDEN];  // per-class sum of x x^T
__device__ float g_sum[N_CLASS * HIDDEN];         // per-class sum of x
__device__ int   g_n[N_CLASS];                    // per-class count

// ---------------- Stage A: per-class raw statistics ----------------
// grid (N_CLASS, 4): class c, column quarter h (32 cols each).
// 256 threads, interleaved tiles (conflict-free scalar LDS):
//   rows: ty + 16*ri (ri<8), cols: h*32 + tx + 16*ci (ci<2) -> acc[8][2].
__global__ void __launch_bounds__(256, 4) stageA_kernel(
    const float* __restrict__ x, const int* __restrict__ y)
{
    const int c = blockIdx.x;
    const int h = blockIdx.y;

    __shared__ float s_d[2][CHUNK][HIDDEN];
    __shared__ int   s_list[BATCH];
    __shared__ int   s_wsum[8];

    const int tid  = threadIdx.x;
    const int lane = tid & 31;
    const int w    = tid >> 5;
    const int tx   = tid & 15;
    const int ty   = tid >> 4;

    // ---- deterministic in-CTA compaction of sample indices ----
    int loc[8];
    int cnt = 0;
    {
        const int4* y4 = (const int4*)y;
        int4 a = y4[tid * 2];
        int4 b = y4[tid * 2 + 1];
        const int base = tid * 8;
        if (a.x == c) loc[cnt++] = base + 0;
        if (a.y == c) loc[cnt++] = base + 1;
        if (a.z == c) loc[cnt++] = base + 2;
        if (a.w == c) loc[cnt++] = base + 3;
        if (b.x == c) loc[cnt++] = base + 4;
        if (b.y == c) loc[cnt++] = base + 5;
        if (b.z == c) loc[cnt++] = base + 6;
        if (b.w == c) loc[cnt++] = base + 7;
    }
    int inc = cnt;
#pragma unroll
    for (int d = 1; d < 32; d <<= 1) {
        int v = __shfl_up_sync(0xffffffffu, inc, d);
        if (lane >= d) inc += v;
    }
    if (lane == 31) s_wsum[w] = inc;
    __syncthreads();
    int woff = 0, n = 0;
#pragma unroll
    for (int k = 0; k < 8; k++) {
        int s = s_wsum[k];
        if (k < w) woff += s;
        n += s;
    }
    const int off = woff + inc - cnt;
#pragma unroll
    for (int i = 0; i < 8; i++)
        if (i < cnt) s_list[off + i] = loc[i];
    __syncthreads();

    // ---- rank-n accumulation of S = sum x x^T (raw x, zero-padded) ----
    float acc[8][2];
#pragma unroll
    for (int ri = 0; ri < 8; ri++)
#pragma unroll
        for (int ci = 0; ci < 2; ci++) acc[ri][ci] = 0.0f;
    float xsum = 0.0f;   // h==0 blocks: threads < 128 accumulate s_c[tid]

    const float4* x4 = (const float4*)x;
    const int nchunks = (n + CHUNK - 1) / CHUNK;
    const int gs = tid >> 5;   // sample row within chunk
    const int gq = tid & 31;   // float4 within row

    if (nchunks > 0) {
        float4 v = make_float4(0.f, 0.f, 0.f, 0.f);
        if (gs < n) v = x4[s_list[gs] * 32 + gq];
        ((float4*)s_d[0][gs])[gq] = v;
    }

    for (int k = 0; k < nchunks; k++) {
        __syncthreads();
        if (k + 1 < nchunks) {
            const int s0 = (k + 1) * CHUNK;
            float4 v = make_float4(0.f, 0.f, 0.f, 0.f);
            if (s0 + gs < n) v = x4[s_list[s0 + gs] * 32 + gq];
            ((float4*)s_d[(k + 1) & 1][gs])[gq] = v;
        }
        const float (*buf)[HIDDEN] = s_d[k & 1];
#pragma unroll
        for (int s = 0; s < CHUNK; s++) {
            float dr[8], dc[2];
#pragma unroll
            for (int ri = 0; ri < 8; ri++) dr[ri] = buf[s][ty + 16 * ri];
#pragma unroll
            for (int ci = 0; ci < 2; ci++) dc[ci] = buf[s][h * 32 + tx + 16 * ci];
#pragma unroll
            for (int ri = 0; ri < 8; ri++)
#pragma unroll
                for (int ci = 0; ci < 2; ci++)
                    acc[ri][ci] += dr[ri] * dc[ci];
            if (h == 0 && tid < HIDDEN) xsum += buf[s][tid];
        }
    }

    // ---- write per-class stats ----
    float* S = g_S + c * HIDDEN * HIDDEN;
#pragma unroll
    for (int ri = 0; ri < 8; ri++) {
        const int r = ty + 16 * ri;
#pragma unroll
        for (int ci = 0; ci < 2; ci++)
            S[r * HIDDEN + h * 32 + tx + 16 * ci] = acc[ri][ci];
    }
    if (h == 0 && tid < HIDDEN) g_sum[c * HIDDEN + tid] = xsum;
    if (h == 0 && tid == 0)     g_n[c] = n;
}

// ---------------- Stage B: elementwise reconstruction ----------------
// out[c,j] = class_cov[c,j] + S_c - mu_j s_c^T - s_c mu_j^T + n_c mu_j mu_j^T
// grid (N_CLASS, N_CENTER, 4): z selects a 32-row slab. 256 threads x 4 float4.
__global__ void __launch_bounds__(256, 6) stageB_kernel(
    const float* __restrict__ class_mu,   // only class_mu[0] used
    const float* __restrict__ class_cov,
    float* __restrict__ out)
{
    const int c = blockIdx.x;
    const int j = blockIdx.y;
    const int z = blockIdx.z;

    __shared__ float s_mu[HIDDEN];
    __shared__ float s_s[HIDDEN];
    __shared__ float s_n;

    const int tid = threadIdx.x;
    if (tid < HIDDEN) {
        s_mu[tid] = class_mu[j * HIDDEN + tid];
        s_s[tid]  = g_sum[c * HIDDEN + tid];
    }
    if (tid == 0) s_n = (float)g_n[c];
    __syncthreads();

    const float n = s_n;
    const float4* S4   = (const float4*)(g_S + (size_t)c * HIDDEN * HIDDEN);
    const size_t  base = ((size_t)(c * N_CENTER + j)) * HIDDEN * HIDDEN;
    const float4* cov4 = (const float4*)(class_cov + base);
    float4*       out4 = (float4*)(out + base);
    const float4* mu4v = (const float4*)s_mu;
    const float4* ss4v = (const float4*)s_s;

#pragma unroll
    for (int i = 0; i < 4; i++) {
        const int q = z * 1024 + tid + 256 * i;  // float4 index; row = q>>5
        const int r = q >> 5;
        const float mr = s_mu[r];
        const float tr = fmaf(n, mr, -s_s[r]);   // n*mu_r - s_r
        const float4 m4 = mu4v[q & 31];
        const float4 sv = ss4v[q & 31];
        const float4 S  = S4[q];
        const float4 cv = cov4[q];
        float4 o;
        o.x = cv.x + S.x - mr * sv.x + tr * m4.x;
        o.y = cv.y + S.y - mr * sv.y + tr * m4.y;
        o.z = cv.z + S.z - mr * sv.z + tr * m4.z;
        o.w = cv.w + S.w - mr * sv.w + tr * m4.w;
        out4[q] = o;
    }
}

extern "C" void kernel_launch(void* const* d_in, const int* in_sizes, int n_in,
                              void* d_out, int out_size) {
    const float* x         = (const float*)d_in[0];
    const int*   y         = (const int*)d_in[1];
    const float* class_mu  = (const float*)d_in[2];
    const float* class_cov = (const float*)d_in[3];
    float*       out       = (float*)d_out;

    dim3 gridA(N_CLASS, 4);
    stageA_kernel<<<gridA, 256>>>(x, y);
    dim3 gridB(N_CLASS, N_CENTER, 4);
    stageB_kernel<<<gridB, 256>>>(class_mu, class_cov, out);
}

// round 8
// speedup vs baseline: 1.0798x; 1.0798x over previous
#include <cuda_runtime.h>

#define N_CLASS  100
#define N_CENTER 4
#define HIDDEN   128
#define BATCH    2048
#define CHUNK    8

// Scratch (device globals; no runtime allocation allowed).
__device__ float g_S[N_CLASS * HIDDEN * HIDDEN];  // per-class sum of x x^T
__device__ float g_sum[N_CLASS * HIDDEN];         // per-class sum of x
__device__ int   g_n[N_CLASS];                    // per-class count

// ---------------- Stage A: per-class raw statistics ----------------
// grid (N_CLASS, 2): class c, column half h (64 cols each).
// 256 threads as 16x16 interleaved tiles (conflict-free scalar LDS):
//   rows: ty + 16*ri (ri<8), cols: h*64 + tx + 16*ci (ci<4) -> acc[8][4].
__global__ void __launch_bounds__(256, 4) stageA_kernel(
    const float* __restrict__ x, const int* __restrict__ y)
{
    const int c = blockIdx.x;
    const int h = blockIdx.y;

    __shared__ float s_d[2][CHUNK][HIDDEN];
    __shared__ int   s_list[BATCH];
    __shared__ int   s_wsum[8];

    const int tid  = threadIdx.x;
    const int lane = tid & 31;
    const int w    = tid >> 5;
    const int tx   = tid & 15;
    const int ty   = tid >> 4;

    // ---- deterministic in-CTA compaction of sample indices ----
    int loc[8];
    int cnt = 0;
    {
        const int4* y4 = (const int4*)y;
        int4 a = y4[tid * 2];
        int4 b = y4[tid * 2 + 1];
        const int base = tid * 8;
        if (a.x == c) loc[cnt++] = base + 0;
        if (a.y == c) loc[cnt++] = base + 1;
        if (a.z == c) loc[cnt++] = base + 2;
        if (a.w == c) loc[cnt++] = base + 3;
        if (b.x == c) loc[cnt++] = base + 4;
        if (b.y == c) loc[cnt++] = base + 5;
        if (b.z == c) loc[cnt++] = base + 6;
        if (b.w == c) loc[cnt++] = base + 7;
    }
    int inc = cnt;
#pragma unroll
    for (int d = 1; d < 32; d <<= 1) {
        int v = __shfl_up_sync(0xffffffffu, inc, d);
        if (lane >= d) inc += v;
    }
    if (lane == 31) s_wsum[w] = inc;
    __syncthreads();
    int woff = 0, n = 0;
#pragma unroll
    for (int k = 0; k < 8; k++) {
        int s = s_wsum[k];
        if (k < w) woff += s;
        n += s;
    }
    const int off = woff + inc - cnt;
#pragma unroll
    for (int i = 0; i < 8; i++)
        if (i < cnt) s_list[off + i] = loc[i];
    __syncthreads();

    // ---- rank-n accumulation of S = sum x x^T (raw x, zero-padded) ----
    float acc[8][4];
#pragma unroll
    for (int ri = 0; ri < 8; ri++)
#pragma unroll
        for (int ci = 0; ci < 4; ci++) acc[ri][ci] = 0.0f;
    float xsum = 0.0f;   // h==0 blocks: threads < 128 accumulate s_c[tid]

    const float4* x4 = (const float4*)x;
    const int nchunks = (n + CHUNK - 1) / CHUNK;
    const int gs = tid >> 5;   // sample row within chunk
    const int gq = tid & 31;   // float4 within row

    if (nchunks > 0) {
        float4 v = make_float4(0.f, 0.f, 0.f, 0.f);
        if (gs < n) v = x4[s_list[gs] * 32 + gq];
        ((float4*)s_d[0][gs])[gq] = v;
    }

    for (int k = 0; k < nchunks; k++) {
        __syncthreads();
        if (k + 1 < nchunks) {
            const int s0 = (k + 1) * CHUNK;
            float4 v = make_float4(0.f, 0.f, 0.f, 0.f);
            if (s0 + gs < n) v = x4[s_list[s0 + gs] * 32 + gq];
            ((float4*)s_d[(k + 1) & 1][gs])[gq] = v;
        }
        const float (*buf)[HIDDEN] = s_d[k & 1];
#pragma unroll
        for (int s = 0; s < CHUNK; s++) {
            float dr[8], dc[4];
#pragma unroll
            for (int ri = 0; ri < 8; ri++) dr[ri] = buf[s][ty + 16 * ri];
#pragma unroll
            for (int ci = 0; ci < 4; ci++) dc[ci] = buf[s][h * 64 + tx + 16 * ci];
#pragma unroll
            for (int ri = 0; ri < 8; ri++)
#pragma unroll
                for (int ci = 0; ci < 4; ci++)
                    acc[ri][ci] += dr[ri] * dc[ci];
            if (h == 0 && tid < HIDDEN) xsum += buf[s][tid];
        }
    }

    // ---- write per-class stats ----
    float* S = g_S + c * HIDDEN * HIDDEN;
#pragma unroll
    for (int ri = 0; ri < 8; ri++) {
        const int r = ty + 16 * ri;
#pragma unroll
        for (int ci = 0; ci < 4; ci++)
            S[r * HIDDEN + h * 64 + tx + 16 * ci] = acc[ri][ci];
    }
    if (h == 0 && tid < HIDDEN) g_sum[c * HIDDEN + tid] = xsum;
    if (h == 0 && tid == 0)     g_n[c] = n;
}

// ---------------- Stage B: elementwise reconstruction ----------------
// out[c,j] = class_cov[c,j] + S_c - mu_j s_c^T - s_c mu_j^T + n_c mu_j mu_j^T
// grid (N_CLASS, N_CENTER, 4): z selects a 32-row slab. 256 threads x 4 float4.
__global__ void __launch_bounds__(256, 6) stageB_kernel(
    const float* __restrict__ class_mu,   // only class_mu[0] used
    const float* __restrict__ class_cov,
    float* __restrict__ out)
{
    const int c = blockIdx.x;
    const int j = blockIdx.y;
    const int z = blockIdx.z;

    __shared__ float s_mu[HIDDEN];
    __shared__ float s_s[HIDDEN];
    __shared__ float s_n;

    const int tid = threadIdx.x;
    if (tid < HIDDEN) {
        s_mu[tid] = class_mu[j * HIDDEN + tid];
        s_s[tid]  = g_sum[c * HIDDEN + tid];
    }
    if (tid == 0) s_n = (float)g_n[c];
    __syncthreads();

    const float n = s_n;
    const float4* S4   = (const float4*)(g_S + (size_t)c * HIDDEN * HIDDEN);
    const size_t  base = ((size_t)(c * N_CENTER + j)) * HIDDEN * HIDDEN;
    const float4* cov4 = (const float4*)(class_cov + base);
    float4*       out4 = (float4*)(out + base);
    const float4* mu4v = (const float4*)s_mu;
    const float4* ss4v = (const float4*)s_s;

#pragma unroll
    for (int i = 0; i < 4; i++) {
        const int q = z * 1024 + tid + 256 * i;  // float4 index; row = q>>5
        const int r = q >> 5;
        const float mr = s_mu[r];
        const float tr = fmaf(n, mr, -s_s[r]);   // n*mu_r - s_r
        const float4 m4 = mu4v[q & 31];
        const float4 sv = ss4v[q & 31];
        const float4 S  = S4[q];
        const float4 cv = cov4[q];
        float4 o;
        o.x = cv.x + S.x - mr * sv.x + tr * m4.x;
        o.y = cv.y + S.y - mr * sv.y + tr * m4.y;
        o.z = cv.z + S.z - mr * sv.z + tr * m4.z;
        o.w = cv.w + S.w - mr * sv.w + tr * m4.w;
        out4[q] = o;
    }
}

extern "C" void kernel_launch(void* const* d_in, const int* in_sizes, int n_in,
                              void* d_out, int out_size) {
    const float* x         = (const float*)d_in[0];
    const int*   y         = (const int*)d_in[1];
    const float* class_mu  = (const float*)d_in[2];
    const float* class_cov = (const float*)d_in[3];
    float*       out       = (float*)d_out;

    dim3 gridA(N_CLASS, 2);
    stageA_kernel<<<gridA, 256>>>(x, y);
    dim3 gridB(N_CLASS, N_CENTER, 4);
    stageB_kernel<<<gridB, 256>>>(class_mu, class_cov, out);
}

// round 10
// speedup vs baseline: 1.1042x; 1.0226x over previous
#include <cuda_runtime.h>

#define N_CLASS  100
#define N_CENTER 4
#define HIDDEN   128
#define BATCH    2048
#define CHUNK    8

// Scratch (device globals; no runtime allocation allowed).
__device__ float g_S[N_CLASS * HIDDEN * HIDDEN];  // per-class sum of x x^T
__device__ float g_sum[N_CLASS * HIDDEN];         // per-class sum of x
__device__ int   g_n[N_CLASS];                    // per-class count

// ---------------- Stage A: per-class raw statistics ----------------
// grid = N_CLASS (one CTA per class, single wave on 148 SMs).
// 256 threads as 16x16 interleaved tiles (conflict-free scalar LDS):
//   rows: ty + 16*ri (ri<8), cols: tx + 16*ci (ci<8) -> acc[8][8].
__global__ void __launch_bounds__(256, 2) stageA_kernel(
    const float* __restrict__ x, const int* __restrict__ y)
{
    const int c = blockIdx.x;

    __shared__ float s_d[2][CHUNK][HIDDEN];
    __shared__ int   s_list[BATCH];
    __shared__ int   s_wsum[8];

    const int tid  = threadIdx.x;
    const int lane = tid & 31;
    const int w    = tid >> 5;
    const int tx   = tid & 15;
    const int ty   = tid >> 4;

    // ---- deterministic in-CTA compaction of sample indices ----
    int loc[8];
    int cnt = 0;
    {
        const int4* y4 = (const int4*)y;
        int4 a = y4[tid * 2];
        int4 b = y4[tid * 2 + 1];
        const int base = tid * 8;
        if (a.x == c) loc[cnt++] = base + 0;
        if (a.y == c) loc[cnt++] = base + 1;
        if (a.z == c) loc[cnt++] = base + 2;
        if (a.w == c) loc[cnt++] = base + 3;
        if (b.x == c) loc[cnt++] = base + 4;
        if (b.y == c) loc[cnt++] = base + 5;
        if (b.z == c) loc[cnt++] = base + 6;
        if (b.w == c) loc[cnt++] = base + 7;
    }
    int inc = cnt;
#pragma unroll
    for (int d = 1; d < 32; d <<= 1) {
        int v = __shfl_up_sync(0xffffffffu, inc, d);
        if (lane >= d) inc += v;
    }
    if (lane == 31) s_wsum[w] = inc;
    __syncthreads();
    int woff = 0, n = 0;
#pragma unroll
    for (int k = 0; k < 8; k++) {
        int s = s_wsum[k];
        if (k < w) woff += s;
        n += s;
    }
    const int off = woff + inc - cnt;
#pragma unroll
    for (int i = 0; i < 8; i++)
        if (i < cnt) s_list[off + i] = loc[i];
    __syncthreads();

    // ---- rank-n accumulation of S = sum x x^T (raw x, zero-padded) ----
    float acc[8][8];
#pragma unroll
    for (int ri = 0; ri < 8; ri++)
#pragma unroll
        for (int ci = 0; ci < 8; ci++) acc[ri][ci] = 0.0f;
    float xsum = 0.0f;   // threads < 128 accumulate s_c[tid]

    const float4* x4 = (const float4*)x;
    const int nchunks = (n + CHUNK - 1) / CHUNK;
    const int gs = tid >> 5;   // sample row within chunk
    const int gq = tid & 31;   // float4 within row

    if (nchunks > 0) {
        float4 v = make_float4(0.f, 0.f, 0.f, 0.f);
        if (gs < n) v = x4[s_list[gs] * 32 + gq];
        ((float4*)s_d[0][gs])[gq] = v;
    }

    for (int k = 0; k < nchunks; k++) {
        __syncthreads();
        if (k + 1 < nchunks) {
            const int s0 = (k + 1) * CHUNK;
            float4 v = make_float4(0.f, 0.f, 0.f, 0.f);
            if (s0 + gs < n) v = x4[s_list[s0 + gs] * 32 + gq];
            ((float4*)s_d[(k + 1) & 1][gs])[gq] = v;
        }
        const float (*buf)[HIDDEN] = s_d[k & 1];
#pragma unroll
        for (int s = 0; s < CHUNK; s++) {
            float dr[8], dc[8];
#pragma unroll
            for (int ri = 0; ri < 8; ri++) dr[ri] = buf[s][ty + 16 * ri];
#pragma unroll
            for (int ci = 0; ci < 8; ci++) dc[ci] = buf[s][tx + 16 * ci];
#pragma unroll
            for (int ri = 0; ri < 8; ri++)
#pragma unroll
                for (int ci = 0; ci < 8; ci++)
                    acc[ri][ci] += dr[ri] * dc[ci];
            if (tid < HIDDEN) xsum += buf[s][tid];
        }
    }

    // ---- write per-class stats ----
    float* S = g_S + c * HIDDEN * HIDDEN;
#pragma unroll
    for (int ri = 0; ri < 8; ri++) {
        const int r = ty + 16 * ri;
#pragma unroll
        for (int ci = 0; ci < 8; ci++)
            S[r * HIDDEN + tx + 16 * ci] = acc[ri][ci];
    }
    if (tid < HIDDEN) g_sum[c * HIDDEN + tid] = xsum;
    if (tid == 0)     g_n[c] = n;
}

// ---------------- Stage B: elementwise reconstruction ----------------
// out[c,j] = class_cov[c,j] + S_c - mu_j s_c^T - s_c mu_j^T + n_c mu_j mu_j^T
// grid (N_CLASS, N_CENTER, 4): z selects a 32-row slab. 256 threads x 4 float4,
// with ALL global loads batched before compute (MLP=8 per thread).
__global__ void __launch_bounds__(256, 4) stageB_kernel(
    const float* __restrict__ class_mu,   // only class_mu[0] used
    const float* __restrict__ class_cov,
    float* __restrict__ out)
{
    const int c = blockIdx.x;
    const int j = blockIdx.y;
    const int z = blockIdx.z;

    __shared__ float s_mu[HIDDEN];
    __shared__ float s_s[HIDDEN];
    __shared__ float s_n;

    const int tid = threadIdx.x;
    if (tid < HIDDEN) {
        s_mu[tid] = class_mu[j * HIDDEN + tid];
        s_s[tid]  = g_sum[c * HIDDEN + tid];
    }
    if (tid == 0) s_n = (float)g_n[c];

    const float4* S4   = (const float4*)(g_S + (size_t)c * HIDDEN * HIDDEN);
    const size_t  base = ((size_t)(c * N_CENTER + j)) * HIDDEN * HIDDEN;
    const float4* cov4 = (const float4*)(class_cov + base);
    float4*       out4 = (float4*)(out + base);

    // Batch ALL 8 global loads first (independent of smem init above).
    const int q0 = z * 1024 + tid;
    float4 Sv[4], cv[4];
#pragma unroll
    for (int i = 0; i < 4; i++) Sv[i] = S4[q0 + 256 * i];
#pragma unroll
    for (int i = 0; i < 4; i++) cv[i] = cov4[q0 + 256 * i];

    __syncthreads();
    const float n = s_n;
    const float4* mu4v = (const float4*)s_mu;
    const float4* ss4v = (const float4*)s_s;
    const float4 m4 = mu4v[tid & 31];   // column vector chunk (same for all i)
    const float4 sv = ss4v[tid & 31];

#pragma unroll
    for (int i = 0; i < 4; i++) {
        const int q = q0 + 256 * i;
        const int r = q >> 5;
        const float mr = s_mu[r];
        const float tr = fmaf(n, mr, -s_s[r]);   // n*mu_r - s_r
        float4 o;
        o.x = cv[i].x + Sv[i].x - mr * sv.x + tr * m4.x;
        o.y = cv[i].y + Sv[i].y - mr * sv.y + tr * m4.y;
        o.z = cv[i].z + Sv[i].z - mr * sv.z + tr * m4.z;
        o.w = cv[i].w + Sv[i].w - mr * sv.w + tr * m4.w;
        out4[q] = o;
    }
}

extern "C" void kernel_launch(void* const* d_in, const int* in_sizes, int n_in,
                              void* d_out, int out_size) {
    const float* x         = (const float*)d_in[0];
    const int*   y         = (const int*)d_in[1];
    const float* class_mu  = (const float*)d_in[2];
    const float* class_cov = (const float*)d_in[3];
    float*       out       = (float*)d_out;

    stageA_kernel<<<N_CLASS, 256>>>(x, y);
    dim3 gridB(N_CLASS, N_CENTER, 4);
    stageB_kernel<<<gridB, 256>>>(class_mu, class_cov, out);
}